// round 11
// baseline (speedup 1.0000x reference)
#include <cuda_runtime.h>
#include <cuda_fp16.h>
#include <cstdint>

// Problem shape
constexpr int B = 16;
constexpr int N = 2048;
constexpr int D = 512;

// Tiling
constexpr int BM = 64;            // query rows per CTA
constexpr int BN = 128;           // key rows per tile (two 64-row halves)
constexpr int NT = N / BN;        // 16 key tiles
constexpr int MBLOCKS = N / BM;   // 32
constexpr int THREADS = 512;      // 16 warps

// Padded leading dims (halfs). Stride must be an odd multiple of 16B.
constexpr int QLD = D + 8;        // 520 -> 1040B rows
constexpr int PLD = BN + 8;       // 136 -> 272B rows

// Shared memory layout (bytes)
constexpr int OFF_Q  = 0;
constexpr int SZ_Q   = BM * QLD * 2;        // 66560
constexpr int OFF_K  = OFF_Q + SZ_Q;        // 66560
constexpr int SZ_K   = BN * QLD * 2;        // 133120
constexpr int OFF_P  = OFF_K + SZ_K;        // 199680
constexpr int SZ_P   = BM * PLD * 2;        // 17408
constexpr int OFF_KN = OFF_P + SZ_P;        // 217088 (128 floats)
constexpr int OFF_L  = OFF_KN + 512;        // 217600 (64 floats)
constexpr int SMEM_BYTES = OFF_L + 256;     // 217856 (<= 232448)

// Scratch: normalized x (fp16) and per-row L2 norms
__device__ __half xn_g[(size_t)B * N * D];
__device__ float  norm_g[B * N];

// ---------------------------------------------------------------------------
// PTX helpers
// ---------------------------------------------------------------------------
__device__ __forceinline__ void cpasync16(uint32_t dst, const void* src) {
    asm volatile("cp.async.cg.shared.global [%0], [%1], 16;" :: "r"(dst), "l"(src));
}
__device__ __forceinline__ void cp_commit() { asm volatile("cp.async.commit_group;"); }
template <int K> __device__ __forceinline__ void cp_wait() {
    asm volatile("cp.async.wait_group %0;" :: "n"(K));
}
__device__ __forceinline__ void bar_sync(int id, int cnt) {
    asm volatile("bar.sync %0, %1;" :: "r"(id), "r"(cnt) : "memory");
}
__device__ __forceinline__ void ldsm4(uint32_t* r, uint32_t a) {
    asm volatile("ldmatrix.sync.aligned.m8n8.x4.shared.b16 {%0,%1,%2,%3}, [%4];"
                 : "=r"(r[0]), "=r"(r[1]), "=r"(r[2]), "=r"(r[3]) : "r"(a));
}
__device__ __forceinline__ void ldsm4t(uint32_t* r, uint32_t a) {
    asm volatile("ldmatrix.sync.aligned.m8n8.x4.trans.shared.b16 {%0,%1,%2,%3}, [%4];"
                 : "=r"(r[0]), "=r"(r[1]), "=r"(r[2]), "=r"(r[3]) : "r"(a));
}
__device__ __forceinline__ void mma16816(float* c, const uint32_t* a,
                                         uint32_t b0, uint32_t b1) {
    asm volatile(
        "mma.sync.aligned.m16n8k16.row.col.f32.f16.f16.f32 "
        "{%0,%1,%2,%3},{%4,%5,%6,%7},{%8,%9},{%0,%1,%2,%3};"
        : "+f"(c[0]), "+f"(c[1]), "+f"(c[2]), "+f"(c[3])
        : "r"(a[0]), "r"(a[1]), "r"(a[2]), "r"(a[3]), "r"(b0), "r"(b1));
}
// ldmatrix x4 address: tiles [r0-7|c0-7, r8-15|c0-7, r0-7|c8-15, r8-15|c8-15]
__device__ __forceinline__ uint32_t ldsm_addr(uint32_t base, int row, int col,
                                              int ld, int lane) {
    int r = row + (lane & 15);
    int c = col + ((lane >> 4) << 3);
    return base + (uint32_t)(r * ld + c) * 2;
}

// ---------------------------------------------------------------------------
// Kernel 1: per-row L2 norm + fp16 normalize.  grid = B*N blocks, 128 threads.
// ---------------------------------------------------------------------------
__global__ void normalize_kernel(const float* __restrict__ x) {
    const int row = blockIdx.x;
    const float* xr = x + (size_t)row * D;
    const int t = threadIdx.x;

    float4 v = reinterpret_cast<const float4*>(xr)[t];
    float s = v.x * v.x + v.y * v.y + v.z * v.z + v.w * v.w;
    #pragma unroll
    for (int o = 16; o > 0; o >>= 1) s += __shfl_down_sync(0xffffffffu, s, o);

    __shared__ float ws[4];
    __shared__ float inv_sh;
    if ((t & 31) == 0) ws[t >> 5] = s;
    __syncthreads();
    if (t == 0) {
        float tot = ws[0] + ws[1] + ws[2] + ws[3];
        float nm = sqrtf(tot);
        norm_g[row] = nm;
        inv_sh = 1.0f / fmaxf(nm, 1e-20f);
    }
    __syncthreads();
    const float inv = inv_sh;

    __half2* o2 = reinterpret_cast<__half2*>(xn_g + (size_t)row * D);
    o2[2 * t + 0] = __floats2half2_rn(v.x * inv, v.y * inv);
    o2[2 * t + 1] = __floats2half2_rn(v.z * inv, v.w * inv);
}

// ---------------------------------------------------------------------------
// Kernel 2: fused attention, 512 threads (16 warps), manual mma.
// S warp grid 4x4 (16x32 tiles); PV: warp owns a 32-col D slice.
// ---------------------------------------------------------------------------
__global__ void __launch_bounds__(THREADS, 1)
attn_kernel(float* __restrict__ out) {
    extern __shared__ char smem[];
    __half* Qs   = reinterpret_cast<__half*>(smem + OFF_Q);
    float*  knrm = reinterpret_cast<float*>(smem + OFF_KN);
    float*  lsh  = reinterpret_cast<float*>(smem + OFF_L);
    const uint32_t Qu = (uint32_t)__cvta_generic_to_shared(smem + OFF_Q);
    const uint32_t Ku = (uint32_t)__cvta_generic_to_shared(smem + OFF_K);
    const uint32_t Pu = (uint32_t)__cvta_generic_to_shared(smem + OFF_P);
    __half* Ps = reinterpret_cast<__half*>(smem + OFF_P);

    const int b  = blockIdx.x / MBLOCKS;
    const int m0 = (blockIdx.x % MBLOCKS) * BM;

    const __half* Xn = xn_g + (size_t)b * N * D;
    const float*  Nv = norm_g + (size_t)b * N;

    const int tid  = threadIdx.x;
    const int warp = tid >> 5;
    const int lane = tid & 31;

    // S-phase warp tile: 16 rows x 32 keys; 4x4 warp grid over 64x128
    const int sr0 = 16 * (warp >> 2);
    const int sn0 = 32 * (warp & 3);
    const bool grpA = (warp & 3) < 2;        // warps whose S keys are in half A
    // group-local thread id 0..255 (grpX = 8 warps)
    const int gtid = ((warp >> 2) * 2 + (warp & 1)) * 32 + lane;
    const int d0 = warp * 32;                // PV D-slice (32 cols)

    // group half-tile loader: 64 rows x 64 segs(16B) over 256 threads = 16 each
    auto load_Khalf = [&](int keybase, int half) {
        const char* src = reinterpret_cast<const char*>(Xn + (size_t)(keybase + half * 64) * D);
        uint32_t dst = Ku + (uint32_t)(half * 64 * QLD) * 2;
        #pragma unroll
        for (int i = 0; i < 16; i++) {
            int idx = gtid + i * 256;
            int r = idx >> 6, sg = idx & 63;
            cpasync16(dst + (uint32_t)(r * QLD + sg * 8) * 2,
                      src + (size_t)r * (D * 2) + sg * 16);
        }
    };

    // ---- prologue: K(0) full tile (all threads), Q, norms, l ----
    {
        const char* src = reinterpret_cast<const char*>(Xn);
        #pragma unroll
        for (int i = 0; i < 16; i++) {
            int idx = tid + i * THREADS;
            int r = idx >> 6, sg = idx & 63;
            cpasync16(Ku + (uint32_t)(r * QLD + sg * 8) * 2,
                      src + (size_t)r * (D * 2) + sg * 16);
        }
        cp_commit();
        const int4* qsrc = reinterpret_cast<const int4*>(Xn + (size_t)m0 * D);
        #pragma unroll
        for (int i = 0; i < 8; i++) {
            int idx = tid + i * THREADS;
            int r = idx >> 6, seg = idx & 63;
            reinterpret_cast<int4*>(Qs + r * QLD)[seg] = qsrc[idx];
        }
        if (tid < BM) lsh[tid] = 0.0f;
        if (tid < BN) knrm[tid] = __ldg(&Nv[tid]);
        cp_wait<0>();
        __syncthreads();
    }

    // O accumulators: 4 row-frags x 4 col-octets x 4 f32 = 64 regs
    float o[4][4][4];
    #pragma unroll
    for (int rf = 0; rf < 4; rf++)
        #pragma unroll
        for (int nf = 0; nf < 4; nf++)
            #pragma unroll
            for (int q = 0; q < 4; q++) o[rf][nf][q] = 0.0f;

    for (int t = 0; t < NT; t++) {
        // ==== S phase: sacc[nf] = Q(16 rows) x K^T(32 keys) ====
        float sacc[4][4];
        #pragma unroll
        for (int nf = 0; nf < 4; nf++)
            #pragma unroll
            for (int q = 0; q < 4; q++) sacc[nf][q] = 0.0f;

        #pragma unroll 8
        for (int k = 0; k < D; k += 16) {
            uint32_t a[4], b0[4], b1[4];
            ldsm4(a,  ldsm_addr(Qu, sr0,      k, QLD, lane));
            ldsm4(b0, ldsm_addr(Ku, sn0,      k, QLD, lane));   // keys sn0..+15
            ldsm4(b1, ldsm_addr(Ku, sn0 + 16, k, QLD, lane));   // keys +16..+31
            mma16816(sacc[0], a, b0[0], b0[2]);
            mma16816(sacc[1], a, b0[1], b0[3]);
            mma16816(sacc[2], a, b1[0], b1[2]);
            mma16816(sacc[3], a, b1[1], b1[3]);
        }

        // ==== register softmax: e = exp(s-1); P = e * |x_j|; l += rowsum(e) ====
        {
            float rs0 = 0.0f, rs1 = 0.0f;
            const int rr = sr0 + (lane >> 2);
            #pragma unroll
            for (int nf = 0; nf < 4; nf++) {
                const int n = sn0 + nf * 8 + 2 * (lane & 3);
                const float kn0 = knrm[n], kn1 = knrm[n + 1];
                float e0 = __expf(sacc[nf][0] - 1.0f);
                float e1 = __expf(sacc[nf][1] - 1.0f);
                float e2 = __expf(sacc[nf][2] - 1.0f);
                float e3 = __expf(sacc[nf][3] - 1.0f);
                rs0 += e0 + e1;
                rs1 += e2 + e3;
                *reinterpret_cast<__half2*>(&Ps[rr * PLD + n]) =
                    __floats2half2_rn(e0 * kn0, e1 * kn1);
                *reinterpret_cast<__half2*>(&Ps[(rr + 8) * PLD + n]) =
                    __floats2half2_rn(e2 * kn0, e3 * kn1);
            }
            rs0 += __shfl_xor_sync(0xffffffffu, rs0, 1, 4);
            rs0 += __shfl_xor_sync(0xffffffffu, rs0, 2, 4);
            rs1 += __shfl_xor_sync(0xffffffffu, rs1, 1, 4);
            rs1 += __shfl_xor_sync(0xffffffffu, rs1, 2, 4);
            if ((lane & 3) == 0) {
                atomicAdd(&lsh[rr], rs0);
                atomicAdd(&lsh[rr + 8], rs1);
            }
        }
        __syncthreads();    // P visible to all; K(t) still live

        float knv = 0.0f;

        // ==== PV half A: keys 0..63 of this tile ====
        #pragma unroll
        for (int kk = 0; kk < 64; kk += 16) {
            uint32_t pa[4][4];
            #pragma unroll
            for (int rf = 0; rf < 4; rf++)
                ldsm4(pa[rf], ldsm_addr(Pu, rf * 16, kk, PLD, lane));
            #pragma unroll
            for (int g = 0; g < 2; g++) {
                uint32_t vb[4];
                ldsm4t(vb, ldsm_addr(Ku, kk, d0 + g * 16, QLD, lane));
                #pragma unroll
                for (int rf = 0; rf < 4; rf++) {
                    mma16816(o[rf][2 * g + 0], pa[rf], vb[0], vb[1]);
                    mma16816(o[rf][2 * g + 1], pa[rf], vb[2], vb[3]);
                }
            }
        }
        __syncthreads();    // all warps done reading K half A
        if (t + 1 < NT && grpA) {
            load_Khalf((t + 1) * BN, 0);
            cp_commit();
            if (gtid < 64) knv = __ldg(&Nv[(t + 1) * BN + gtid]);
        }

        // ==== PV half B: keys 64..127 (overlaps KA' load) ====
        #pragma unroll
        for (int kk = 64; kk < 128; kk += 16) {
            uint32_t pa[4][4];
            #pragma unroll
            for (int rf = 0; rf < 4; rf++)
                ldsm4(pa[rf], ldsm_addr(Pu, rf * 16, kk, PLD, lane));
            #pragma unroll
            for (int g = 0; g < 2; g++) {
                uint32_t vb[4];
                ldsm4t(vb, ldsm_addr(Ku, kk, d0 + g * 16, QLD, lane));
                #pragma unroll
                for (int rf = 0; rf < 4; rf++) {
                    mma16816(o[rf][2 * g + 0], pa[rf], vb[0], vb[1]);
                    mma16816(o[rf][2 * g + 1], pa[rf], vb[2], vb[3]);
                }
            }
        }
        __syncthreads();    // all warps done reading K half B; P free

        if (t + 1 < NT) {
            if (!grpA) {
                load_Khalf((t + 1) * BN, 1);
                cp_commit();
                if (gtid < 64) knv = __ldg(&Nv[(t + 1) * BN + 64 + gtid]);
            }
            cp_wait<0>();   // own group's half complete
            if (gtid < 64) knrm[(grpA ? 0 : 64) + gtid] = knv;
            bar_sync(grpA ? 1 : 2, 256);   // group-local: half + norms visible
        }
    }

    // ==== epilogue: scale by 1/l, direct global float2 stores ====
    float* outB = out + ((size_t)b * N + m0) * D;
    #pragma unroll
    for (int rf = 0; rf < 4; rf++) {
        const int rr = rf * 16 + (lane >> 2);
        const float i0 = 1.0f / lsh[rr];
        const float i1 = 1.0f / lsh[rr + 8];
        #pragma unroll
        for (int nf = 0; nf < 4; nf++) {
            const int cc = d0 + nf * 8 + 2 * (lane & 3);
            float2 v0 = make_float2(o[rf][nf][0] * i0, o[rf][nf][1] * i0);
            float2 v1 = make_float2(o[rf][nf][2] * i1, o[rf][nf][3] * i1);
            *reinterpret_cast<float2*>(&outB[(size_t)rr * D + cc]) = v0;
            *reinterpret_cast<float2*>(&outB[(size_t)(rr + 8) * D + cc]) = v1;
        }
    }
}

// ---------------------------------------------------------------------------
extern "C" void kernel_launch(void* const* d_in, const int* in_sizes, int n_in,
                              void* d_out, int out_size) {
    (void)in_sizes; (void)n_in; (void)out_size;
    const float* x = reinterpret_cast<const float*>(d_in[0]);
    float* out = reinterpret_cast<float*>(d_out);

    cudaFuncSetAttribute(attn_kernel,
                         cudaFuncAttributeMaxDynamicSharedMemorySize, SMEM_BYTES);

    normalize_kernel<<<B * N, 128>>>(x);
    attn_kernel<<<B * MBLOCKS, THREADS, SMEM_BYTES>>>(out);
}

// round 15
// speedup vs baseline: 1.1218x; 1.1218x over previous
#include <cuda_runtime.h>
#include <cuda_fp16.h>
#include <cstdint>

// Problem shape
constexpr int B = 16;
constexpr int N = 2048;
constexpr int D = 512;

// GEMM tiling
constexpr int TM = 128;          // CTA tile M
constexpr int TN = 128;          // CTA tile N
constexpr int KC = 32;           // k-chunk (halfs)
constexpr int THREADS = 256;     // 8 warps, 2x4 warp grid, warp tile 64x32

// smem strides (halfs); row strides are odd multiples of 16B -> conflict-free ldsm
constexpr int ALD  = KC + 8;     // 40 halfs = 80B
constexpr int BLD2 = TN + 8;     // 136 halfs = 272B

constexpr int G1_STAGE = 2 * (TM * ALD * 2);            // A + B : 20480 B
constexpr int G2_STAGE = TM * ALD * 2 + KC * BLD2 * 2;  // A + B : 18944 B
constexpr int SMEM1 = 3 * G1_STAGE;                     // 61440
constexpr int SMEM2 = 3 * G2_STAGE;                     // 56832

// Scratch
__device__ __half xn_g[(size_t)B * N * D];    // normalized x, fp16 (32MB)
__device__ __half xf_g[(size_t)B * N * D];    // raw x, fp16 (32MB)
__device__ __half P_g[(size_t)B * N * N];     // exp scores, fp16 (128MB)
__device__ float  l_g[B * N];                 // softmax denominators

// ---------------------------------------------------------------------------
// PTX helpers
// ---------------------------------------------------------------------------
__device__ __forceinline__ void cpasync16(uint32_t dst, const void* src) {
    asm volatile("cp.async.cg.shared.global [%0], [%1], 16;" :: "r"(dst), "l"(src));
}
__device__ __forceinline__ void cp_commit() { asm volatile("cp.async.commit_group;"); }
template <int K> __device__ __forceinline__ void cp_wait() {
    asm volatile("cp.async.wait_group %0;" :: "n"(K));
}
__device__ __forceinline__ void ldsm4(uint32_t* r, uint32_t a) {
    asm volatile("ldmatrix.sync.aligned.m8n8.x4.shared.b16 {%0,%1,%2,%3}, [%4];"
                 : "=r"(r[0]), "=r"(r[1]), "=r"(r[2]), "=r"(r[3]) : "r"(a));
}
__device__ __forceinline__ void ldsm4t(uint32_t* r, uint32_t a) {
    asm volatile("ldmatrix.sync.aligned.m8n8.x4.trans.shared.b16 {%0,%1,%2,%3}, [%4];"
                 : "=r"(r[0]), "=r"(r[1]), "=r"(r[2]), "=r"(r[3]) : "r"(a));
}
__device__ __forceinline__ void mma16816(float* c, const uint32_t* a,
                                         uint32_t b0, uint32_t b1) {
    asm volatile(
        "mma.sync.aligned.m16n8k16.row.col.f32.f16.f16.f32 "
        "{%0,%1,%2,%3},{%4,%5,%6,%7},{%8,%9},{%0,%1,%2,%3};"
        : "+f"(c[0]), "+f"(c[1]), "+f"(c[2]), "+f"(c[3])
        : "r"(a[0]), "r"(a[1]), "r"(a[2]), "r"(a[3]), "r"(b0), "r"(b1));
}
__device__ __forceinline__ uint32_t ldsm_addr(uint32_t base, int row, int col,
                                              int ld, int lane) {
    int r = row + (lane & 15);
    int c = col + ((lane >> 4) << 3);
    return base + (uint32_t)(r * ld + c) * 2;
}

// ---------------------------------------------------------------------------
// Kernel 1: norms -> xn (normalized fp16), xf (raw fp16), zero l.
// ---------------------------------------------------------------------------
__global__ void prep_kernel(const float* __restrict__ x) {
    const int row = blockIdx.x;
    const int t = threadIdx.x;
    float4 v = reinterpret_cast<const float4*>(x + (size_t)row * D)[t];
    float s = v.x * v.x + v.y * v.y + v.z * v.z + v.w * v.w;
    #pragma unroll
    for (int o = 16; o > 0; o >>= 1) s += __shfl_down_sync(0xffffffffu, s, o);
    __shared__ float ws[4];
    __shared__ float inv_sh;
    if ((t & 31) == 0) ws[t >> 5] = s;
    __syncthreads();
    if (t == 0) {
        float tot = ws[0] + ws[1] + ws[2] + ws[3];
        inv_sh = rsqrtf(fmaxf(tot, 1e-30f));
        l_g[row] = 0.0f;
    }
    __syncthreads();
    const float inv = inv_sh;

    __half2* on = reinterpret_cast<__half2*>(xn_g + (size_t)row * D);
    __half2* of = reinterpret_cast<__half2*>(xf_g + (size_t)row * D);
    on[2 * t + 0] = __floats2half2_rn(v.x * inv, v.y * inv);
    on[2 * t + 1] = __floats2half2_rn(v.z * inv, v.w * inv);
    of[2 * t + 0] = __floats2half2_rn(v.x, v.y);
    of[2 * t + 1] = __floats2half2_rn(v.z, v.w);
}

// ---------------------------------------------------------------------------
// GEMM1: C[128x128] = xn[m,:] . xn[n,:]^T (K=512); epilogue exp(c-1) -> P, l.
// grid (16 nt, 16 mt, 16 b), 256 threads, 2 CTAs/SM.
// ---------------------------------------------------------------------------
__global__ void __launch_bounds__(THREADS, 2)
gemm1_kernel() {
    extern __shared__ char smem[];
    const uint32_t su = (uint32_t)__cvta_generic_to_shared(smem);

    const int nt = blockIdx.x, mt = blockIdx.y, b = blockIdx.z;
    const int m0 = mt * TM, n0 = nt * TN;

    const __half* Abase = xn_g + ((size_t)b * N + m0) * D;
    const __half* Bbase = xn_g + ((size_t)b * N + n0) * D;

    const int tid  = threadIdx.x;
    const int warp = tid >> 5;
    const int lane = tid & 31;
    const int wr0 = (warp >> 2) * 64;     // warp rows (M)
    const int wc0 = (warp & 3) * 32;      // warp cols (N)

    auto load_chunk = [&](int c, int stg) {
        const uint32_t base = su + (uint32_t)stg * G1_STAGE;
        #pragma unroll
        for (int j = 0; j < 2; j++) {
            int idx = tid + j * THREADS;          // 0..511
            int r = idx >> 2, sg = idx & 3;
            cpasync16(base + (uint32_t)(r * ALD + sg * 8) * 2,
                      Abase + (size_t)r * D + c * KC + sg * 8);
            cpasync16(base + (uint32_t)(TM * ALD + r * ALD + sg * 8) * 2,
                      Bbase + (size_t)r * D + c * KC + sg * 8);
        }
    };

    constexpr int NC = D / KC;   // 16
    load_chunk(0, 0); cp_commit();
    load_chunk(1, 1); cp_commit();

    float o[4][4][4];
    #pragma unroll
    for (int rf = 0; rf < 4; rf++)
        #pragma unroll
        for (int nf = 0; nf < 4; nf++)
            #pragma unroll
            for (int q = 0; q < 4; q++) o[rf][nf][q] = 0.0f;

    for (int c = 0; c < NC; c++) {
        // Prefetch chunk c+2, then wait so that chunk c is RESIDENT.
        // Outstanding after commit: {c+1, c+2} -> wait<2>; tails: wait<1>/wait<0>.
        if (c + 2 < NC) {
            load_chunk(c + 2, (c + 2) % 3); cp_commit();
            cp_wait<2>();
        } else if (c + 1 < NC) {
            cp_wait<1>();
        } else {
            cp_wait<0>();
        }
        __syncthreads();

        const uint32_t Au = su + (uint32_t)(c % 3) * G1_STAGE;
        const uint32_t Bu = Au + (uint32_t)(TM * ALD) * 2;
        #pragma unroll
        for (int ks = 0; ks < 2; ks++) {
            const int k = ks * 16;
            uint32_t a[4][4], b0[4], b1[4];
            #pragma unroll
            for (int rf = 0; rf < 4; rf++)
                ldsm4(a[rf], ldsm_addr(Au, wr0 + rf * 16, k, ALD, lane));
            ldsm4(b0, ldsm_addr(Bu, wc0,      k, ALD, lane));
            ldsm4(b1, ldsm_addr(Bu, wc0 + 16, k, ALD, lane));
            #pragma unroll
            for (int rf = 0; rf < 4; rf++) {
                mma16816(o[rf][0], a[rf], b0[0], b0[2]);
                mma16816(o[rf][1], a[rf], b0[1], b0[3]);
                mma16816(o[rf][2], a[rf], b1[0], b1[2]);
                mma16816(o[rf][3], a[rf], b1[1], b1[3]);
            }
        }
        __syncthreads();   // all warps done with chunk c before its stage is reused
    }

    // epilogue: P = exp(c-1) fp16; l row sums (global atomics)
    #pragma unroll
    for (int rf = 0; rf < 4; rf++) {
        const int rr = wr0 + rf * 16 + (lane >> 2);
        float rs0 = 0.0f, rs1 = 0.0f;
        __half* Prow = P_g + ((size_t)b * N + m0 + rr) * N + n0;
        #pragma unroll
        for (int nf = 0; nf < 4; nf++) {
            const int nn = wc0 + nf * 8 + 2 * (lane & 3);
            float e0 = __expf(o[rf][nf][0] - 1.0f);
            float e1 = __expf(o[rf][nf][1] - 1.0f);
            float e2 = __expf(o[rf][nf][2] - 1.0f);
            float e3 = __expf(o[rf][nf][3] - 1.0f);
            rs0 += e0 + e1;
            rs1 += e2 + e3;
            *reinterpret_cast<__half2*>(Prow + nn)         = __floats2half2_rn(e0, e1);
            *reinterpret_cast<__half2*>(Prow + 8 * N + nn) = __floats2half2_rn(e2, e3);
        }
        rs0 += __shfl_xor_sync(0xffffffffu, rs0, 1, 4);
        rs0 += __shfl_xor_sync(0xffffffffu, rs0, 2, 4);
        rs1 += __shfl_xor_sync(0xffffffffu, rs1, 1, 4);
        rs1 += __shfl_xor_sync(0xffffffffu, rs1, 2, 4);
        if ((lane & 3) == 0) {
            atomicAdd(&l_g[b * N + m0 + rr], rs0);
            atomicAdd(&l_g[b * N + m0 + rr + 8], rs1);
        }
    }
}

// ---------------------------------------------------------------------------
// GEMM2: O[128 rows x 128 d-cols] = P[rows, :2048] . x[:, d-cols], /l.
// grid (4 dt, 16 nt, 16 b), 256 threads, 2 CTAs/SM.
// ---------------------------------------------------------------------------
__global__ void __launch_bounds__(THREADS, 2)
gemm2_kernel(float* __restrict__ out) {
    extern __shared__ char smem[];
    const uint32_t su = (uint32_t)__cvta_generic_to_shared(smem);

    const int dt = blockIdx.x, nt = blockIdx.y, b = blockIdx.z;
    const int d0c = dt * TN, n0 = nt * TM;

    const __half* Abase = P_g + ((size_t)b * N + n0) * N;   // k = key index, stride N
    const __half* Bx    = xf_g + (size_t)b * N * D;

    const int tid  = threadIdx.x;
    const int warp = tid >> 5;
    const int lane = tid & 31;
    const int wr0 = (warp >> 2) * 64;
    const int wc0 = (warp & 3) * 32;

    auto load_chunk = [&](int c, int stg) {
        const uint32_t base = su + (uint32_t)stg * G2_STAGE;
        #pragma unroll
        for (int j = 0; j < 2; j++) {
            int idx = tid + j * THREADS;
            int r = idx >> 2, sg = idx & 3;
            cpasync16(base + (uint32_t)(r * ALD + sg * 8) * 2,
                      Abase + (size_t)r * N + c * KC + sg * 8);
            int r2 = idx >> 4, sg2 = idx & 15;
            cpasync16(base + (uint32_t)(TM * ALD + r2 * BLD2 + sg2 * 8) * 2,
                      Bx + (size_t)(c * KC + r2) * D + d0c + sg2 * 8);
        }
    };

    constexpr int NC = N / KC;   // 64
    load_chunk(0, 0); cp_commit();
    load_chunk(1, 1); cp_commit();

    float o[4][4][4];
    #pragma unroll
    for (int rf = 0; rf < 4; rf++)
        #pragma unroll
        for (int nf = 0; nf < 4; nf++)
            #pragma unroll
            for (int q = 0; q < 4; q++) o[rf][nf][q] = 0.0f;

    for (int c = 0; c < NC; c++) {
        if (c + 2 < NC) {
            load_chunk(c + 2, (c + 2) % 3); cp_commit();
            cp_wait<2>();
        } else if (c + 1 < NC) {
            cp_wait<1>();
        } else {
            cp_wait<0>();
        }
        __syncthreads();

        const uint32_t Au = su + (uint32_t)(c % 3) * G2_STAGE;
        const uint32_t Bu = Au + (uint32_t)(TM * ALD) * 2;
        #pragma unroll
        for (int ks = 0; ks < 2; ks++) {
            const int k = ks * 16;
            uint32_t a[4][4];
            #pragma unroll
            for (int rf = 0; rf < 4; rf++)
                ldsm4(a[rf], ldsm_addr(Au, wr0 + rf * 16, k, ALD, lane));
            #pragma unroll
            for (int g = 0; g < 2; g++) {
                uint32_t vb[4];
                ldsm4t(vb, ldsm_addr(Bu, k, wc0 + g * 16, BLD2, lane));
                #pragma unroll
                for (int rf = 0; rf < 4; rf++) {
                    mma16816(o[rf][2 * g + 0], a[rf], vb[0], vb[1]);
                    mma16816(o[rf][2 * g + 1], a[rf], vb[2], vb[3]);
                }
            }
        }
        __syncthreads();   // all warps done with chunk c before its stage is reused
    }

    // epilogue: scale by 1/l, write fp32
    #pragma unroll
    for (int rf = 0; rf < 4; rf++) {
        const int rr = wr0 + rf * 16 + (lane >> 2);
        const float i0 = 1.0f / __ldg(&l_g[b * N + n0 + rr]);
        const float i1 = 1.0f / __ldg(&l_g[b * N + n0 + rr + 8]);
        float* Orow = out + ((size_t)b * N + n0 + rr) * D + d0c;
        #pragma unroll
        for (int nf = 0; nf < 4; nf++) {
            const int nn = wc0 + nf * 8 + 2 * (lane & 3);
            *reinterpret_cast<float2*>(Orow + nn) =
                make_float2(o[rf][nf][0] * i0, o[rf][nf][1] * i0);
            *reinterpret_cast<float2*>(Orow + 8 * D + nn) =
                make_float2(o[rf][nf][2] * i1, o[rf][nf][3] * i1);
        }
    }
}

// ---------------------------------------------------------------------------
extern "C" void kernel_launch(void* const* d_in, const int* in_sizes, int n_in,
                              void* d_out, int out_size) {
    (void)in_sizes; (void)n_in; (void)out_size;
    const float* x = reinterpret_cast<const float*>(d_in[0]);
    float* out = reinterpret_cast<float*>(d_out);

    cudaFuncSetAttribute(gemm1_kernel,
                         cudaFuncAttributeMaxDynamicSharedMemorySize, SMEM1);
    cudaFuncSetAttribute(gemm2_kernel,
                         cudaFuncAttributeMaxDynamicSharedMemorySize, SMEM2);

    prep_kernel<<<B * N, 128>>>(x);
    gemm1_kernel<<<dim3(N / TN, N / TM, B), THREADS, SMEM1>>>();
    gemm2_kernel<<<dim3(D / TN, N / TM, B), THREADS, SMEM2>>>(out);
}